// round 5
// baseline (speedup 1.0000x reference)
#include <cuda_runtime.h>
#include <cstdint>

#define BATCH   4
#define NSEQ    2048
#define DMODEL  1024
#define KDIM    32
#define ROWS    (BATCH * NSEQ)
#define CLAMP_V 10.0f

// Scratch: G stored K-MAJOR (g_Gt[k][row]).
__device__ float g_Gt[(size_t)KDIM * ROWS];

// ---- packed f32x2 helpers ---------------------------------------------------
__device__ __forceinline__ unsigned long long pk2(float a, float b) {
    unsigned long long r;
    asm("mov.b64 %0, {%1, %2};" : "=l"(r) : "f"(a), "f"(b));
    return r;
}
__device__ __forceinline__ void unpk2(unsigned long long v, float& a, float& b) {
    asm("mov.b64 {%0, %1}, %2;" : "=f"(a), "=f"(b) : "l"(v));
}
__device__ __forceinline__ unsigned long long fma2(
    unsigned long long a, unsigned long long b, unsigned long long c) {
    unsigned long long d;
    asm("fma.rn.f32x2 %0, %1, %2, %3;" : "=l"(d) : "l"(a), "l"(b), "l"(c));
    return d;
}
__device__ __forceinline__ unsigned long long add2(
    unsigned long long a, unsigned long long b) {
    unsigned long long d;
    asm("add.rn.f32x2 %0, %1, %2;" : "=l"(d) : "l"(a), "l"(b));
    return d;
}
__device__ __forceinline__ unsigned long long mul2(
    unsigned long long a, unsigned long long b) {
    unsigned long long d;
    asm("mul.rn.f32x2 %0, %1, %2;" : "=l"(d) : "l"(a), "l"(b));
    return d;
}

union F4U { float4 f; unsigned long long u[2]; float s[4]; };

// ---- cp.async helpers -------------------------------------------------------
__device__ __forceinline__ void cpasync16(void* smem_ptr, const void* gmem_ptr) {
    unsigned int s = (unsigned int)__cvta_generic_to_shared(smem_ptr);
    asm volatile("cp.async.cg.shared.global [%0], [%1], 16;\n"
                 :: "r"(s), "l"(gmem_ptr) : "memory");
}
__device__ __forceinline__ void cpasync_commit() {
    asm volatile("cp.async.commit_group;\n" ::: "memory");
}
__device__ __forceinline__ void cpasync_wait0() {
    asm volatile("cp.async.wait_group 0;\n" ::: "memory");
}

// ---------------------------------------------------------------------------
// Kernel 1 (k-split): block = 32 rows x 16 k-outputs (kb = blockIdx.y*16).
// 256 threads: ti = tid>>3 -> row (0..31); tj = tid&7 -> k = kb+tj, kb+tj+8.
// Per d4: 3 LDS.128 (h, w0, w1 - all 1 wavefront each) : 8 FFMA.
// Register double-buffered d-chunks of 64. Writes G k-major via smem stage.
// ---------------------------------------------------------------------------
__global__ void __launch_bounds__(256) k1_proj(
    const float* __restrict__ H, const float* __restrict__ W)
{
    __shared__ float Hs[2][32][68];
    __shared__ float Ws[2][16][68];
    __shared__ float Gsm[16][33];

    const int tid = threadIdx.x;
    const int r0  = blockIdx.x * 32;
    const int kb  = blockIdx.y * 16;
    const int ti  = tid >> 3;       // 0..31 -> row
    const int tj  = tid & 7;        // k = kb+tj, kb+tj+8

    float4 hreg[2], wreg;

    // Prologue chunk 0: H tile 32x64 (512 f4, 2/thread), W tile 16x64 (256 f4, 1/thread)
    #pragma unroll
    for (int p = 0; p < 2; p++) {
        const int e  = tid + p * 256;
        const int rr = e >> 4;
        const int cc = (e & 15) * 4;
        hreg[p] = *(const float4*)(H + (size_t)(r0 + rr) * DMODEL + cc);
    }
    {
        const int rr = tid >> 4;
        const int cc = (tid & 15) * 4;
        wreg = *(const float4*)(W + (size_t)(kb + rr) * DMODEL + cc);
    }
    #pragma unroll
    for (int p = 0; p < 2; p++) {
        const int e  = tid + p * 256;
        const int rr = e >> 4;
        const int cc = (e & 15) * 4;
        *(float4*)&Hs[0][rr][cc] = hreg[p];
    }
    {
        const int rr = tid >> 4;
        const int cc = (tid & 15) * 4;
        *(float4*)&Ws[0][rr][cc] = wreg;
    }
    __syncthreads();

    float acc0 = 0.f, acc1 = 0.f;

    for (int c = 0; c < 16; c++) {
        const int buf = c & 1;

        if (c < 15) {
            const int dc = (c + 1) * 64;
            #pragma unroll
            for (int p = 0; p < 2; p++) {
                const int e  = tid + p * 256;
                const int rr = e >> 4;
                const int cc = (e & 15) * 4;
                hreg[p] = *(const float4*)(H + (size_t)(r0 + rr) * DMODEL + dc + cc);
            }
            {
                const int rr = tid >> 4;
                const int cc = (tid & 15) * 4;
                wreg = *(const float4*)(W + (size_t)(kb + rr) * DMODEL + dc + cc);
            }
        }

        #pragma unroll
        for (int d4 = 0; d4 < 64; d4 += 4) {
            const float4 h  = *(const float4*)&Hs[buf][ti][d4];
            const float4 w0 = *(const float4*)&Ws[buf][tj][d4];
            const float4 w1 = *(const float4*)&Ws[buf][tj + 8][d4];
            acc0 += h.x * w0.x; acc0 += h.y * w0.y;
            acc0 += h.z * w0.z; acc0 += h.w * w0.w;
            acc1 += h.x * w1.x; acc1 += h.y * w1.y;
            acc1 += h.z * w1.z; acc1 += h.w * w1.w;
        }
        __syncthreads();

        if (c < 15) {
            #pragma unroll
            for (int p = 0; p < 2; p++) {
                const int e  = tid + p * 256;
                const int rr = e >> 4;
                const int cc = (e & 15) * 4;
                *(float4*)&Hs[buf ^ 1][rr][cc] = hreg[p];
            }
            {
                const int rr = tid >> 4;
                const int cc = (tid & 15) * 4;
                *(float4*)&Ws[buf ^ 1][rr][cc] = wreg;
            }
            __syncthreads();
        }
    }

    // Stage k-major, then coalesced writeout (128B contiguous per k).
    Gsm[tj][ti]     = acc0;
    Gsm[tj + 8][ti] = acc1;
    __syncthreads();

    #pragma unroll
    for (int e = tid; e < 16 * 32; e += 256) {
        const int k = e >> 5;
        const int i = e & 31;
        g_Gt[(size_t)(kb + k) * ROWS + r0 + i] = Gsm[k][i];
    }
}

// ---------------------------------------------------------------------------
// Kernel 2: 64x64 output tile. cp.async-prefetched B_prev tile in smem
// overlaps the FFMA2 gram. Norms computed in-block. Thread tile 4x4.
// ---------------------------------------------------------------------------
__global__ void __launch_bounds__(256, 4) k2_bias(
    const float* __restrict__ Bprev,
    const float* __restrict__ alpha_p,
    const float* __restrict__ beta_p,
    float* __restrict__ out)
{
    __shared__ float Gis[KDIM][64];
    __shared__ float Gjs[KDIM][64];
    __shared__ float Bps[64][68];
    __shared__ float sqi[64];
    __shared__ float sqj[64];

    const int b   = blockIdx.z;
    const int i0  = blockIdx.y * 64;
    const int j0  = blockIdx.x * 64;
    const int gi0 = b * NSEQ + i0;
    const int gj0 = b * NSEQ + j0;
    const int tid = threadIdx.x;

    const float alpha = *alpha_p;
    const float beta  = *beta_p;

    // 1) Async prefetch of the B_prev tile (64x64 f32 = 1024 float4, 4/thread).
    const size_t bbase = ((size_t)b * NSEQ + i0) * NSEQ + j0;
    #pragma unroll
    for (int p = 0; p < 4; p++) {
        const int e   = tid + p * 256;
        const int row = e >> 4;
        const int col = (e & 15) * 4;
        cpasync16(&Bps[row][col], Bprev + bbase + (size_t)row * NSEQ + col);
    }
    cpasync_commit();

    // 2) G tiles: coalesced float4 loads from k-major G (L2-resident).
    #pragma unroll
    for (int e = tid; e < KDIM * 16; e += 256) {
        const int k = e >> 4;
        const int x = (e & 15) * 4;
        *(float4*)&Gis[k][x] = *(const float4*)(g_Gt + (size_t)k * ROWS + gi0 + x);
    }
    #pragma unroll
    for (int e = tid; e < KDIM * 16; e += 256) {
        const int k = e >> 4;
        const int x = (e & 15) * 4;
        *(float4*)&Gjs[k][x] = *(const float4*)(g_Gt + (size_t)k * ROWS + gj0 + x);
    }
    __syncthreads();

    // 3) Row norms from the smem tiles (threads 0..127).
    if (tid < 128) {
        const int col = tid & 63;
        float s = 0.f;
        if (tid < 64) {
            #pragma unroll
            for (int k = 0; k < KDIM; k++) { const float v = Gis[k][col]; s += v * v; }
            sqi[col] = s;
        } else {
            #pragma unroll
            for (int k = 0; k < KDIM; k++) { const float v = Gjs[k][col]; s += v * v; }
            sqj[col] = s;
        }
    }
    __syncthreads();

    const int ti = tid >> 4;    // 0..15 -> i rows ib..ib+3
    const int tj = tid & 15;    // 0..15 -> j cols jb..jb+3
    const int ib = ti * 4;
    const int jb = tj * 4;

    // accp[ip][jj]: i-pair (ib+2ip, ib+2ip+1) x col jb+jj.
    unsigned long long accp[2][4];
    #pragma unroll
    for (int ip = 0; ip < 2; ip++)
        #pragma unroll
        for (int jj = 0; jj < 4; jj++)
            accp[ip][jj] = 0ull;

    #pragma unroll 8
    for (int k = 0; k < KDIM; k++) {
        F4U gi;
        gi.f = *(const float4*)&Gis[k][ib];
        const float4 gj = *(const float4*)&Gjs[k][jb];
        const unsigned long long g0 = pk2(gj.x, gj.x);
        const unsigned long long g1 = pk2(gj.y, gj.y);
        const unsigned long long g2 = pk2(gj.z, gj.z);
        const unsigned long long g3 = pk2(gj.w, gj.w);

        accp[0][0] = fma2(gi.u[0], g0, accp[0][0]);
        accp[0][1] = fma2(gi.u[0], g1, accp[0][1]);
        accp[0][2] = fma2(gi.u[0], g2, accp[0][2]);
        accp[0][3] = fma2(gi.u[0], g3, accp[0][3]);
        accp[1][0] = fma2(gi.u[1], g0, accp[1][0]);
        accp[1][1] = fma2(gi.u[1], g1, accp[1][1]);
        accp[1][2] = fma2(gi.u[1], g2, accp[1][2]);
        accp[1][3] = fma2(gi.u[1], g3, accp[1][3]);
    }

    // 4) Ensure the prefetched B_prev tile is visible to all threads.
    cpasync_wait0();
    __syncthreads();

    // 5) Epilogue: raw = si + sj - 2*acc; ab = alpha*b;
    //    result = clamp(min(ab, fma(-beta, raw, ab)), -10, 10).
    const unsigned long long alpha2   = pk2(alpha, alpha);
    const unsigned long long negbeta2 = pk2(-beta, -beta);
    const unsigned long long negtwo2  = pk2(-2.0f, -2.0f);

    unsigned long long sj2[4];
    #pragma unroll
    for (int jj = 0; jj < 4; jj++) {
        const float s = sqj[jb + jj];
        sj2[jj] = pk2(s, s);
    }

    #pragma unroll
    for (int ip = 0; ip < 2; ip++) {
        const int rl = ib + 2 * ip;
        const unsigned long long si2 = pk2(sqi[rl], sqi[rl + 1]);

        F4U bvl, bvh;
        bvl.f = *(const float4*)&Bps[rl][jb];
        bvh.f = *(const float4*)&Bps[rl + 1][jb];

        F4U rlo, rhi;
        #pragma unroll
        for (int jj = 0; jj < 4; jj++) {
            const unsigned long long sij2 = add2(si2, sj2[jj]);
            const unsigned long long raw2 = fma2(negtwo2, accp[ip][jj], sij2);
            const unsigned long long bp2  = pk2(bvl.s[jj], bvh.s[jj]);
            const unsigned long long ab2  = mul2(alpha2, bp2);
            const unsigned long long t2   = fma2(negbeta2, raw2, ab2);
            float abl, abh, tl, th;
            unpk2(ab2, abl, abh);
            unpk2(t2, tl, th);
            rlo.s[jj] = fminf(fmaxf(fminf(abl, tl), -CLAMP_V), CLAMP_V);
            rhi.s[jj] = fminf(fmaxf(fminf(abh, th), -CLAMP_V), CLAMP_V);
        }
        __stcs((float4*)(out + bbase + (size_t)rl * NSEQ + jb), rlo.f);
        __stcs((float4*)(out + bbase + (size_t)(rl + 1) * NSEQ + jb), rhi.f);
    }
}

// ---------------------------------------------------------------------------
extern "C" void kernel_launch(void* const* d_in, const int* in_sizes, int n_in,
                              void* d_out, int out_size)
{
    const float* H     = (const float*)d_in[0];
    const float* Bprev = (const float*)d_in[1];
    const float* W     = (const float*)d_in[2];
    const float* alpha = (const float*)d_in[3];
    const float* beta  = (const float*)d_in[4];
    float* out = (float*)d_out;

    dim3 g1(ROWS / 32, 2);
    k1_proj<<<g1, 256>>>(H, W);

    dim3 g2(NSEQ / 64, NSEQ / 64, BATCH);
    k2_bias<<<g2, 256>>>(Bprev, alpha, beta, out);
}

// round 9
// speedup vs baseline: 1.3716x; 1.3716x over previous
#include <cuda_runtime.h>
#include <cstdint>

#define BATCH   4
#define NSEQ    2048
#define DMODEL  1024
#define KDIM    32
#define ROWS    (BATCH * NSEQ)
#define CLAMP_V 10.0f

// Scratch: G stored K-MAJOR (g_Gt[k][row]) + per-row squared norms.
__device__ float g_Gt[(size_t)KDIM * ROWS];
__device__ float g_Gsq[ROWS];

// ---- packed f32x2 helpers ---------------------------------------------------
__device__ __forceinline__ unsigned long long pk2(float a, float b) {
    unsigned long long r;
    asm("mov.b64 %0, {%1, %2};" : "=l"(r) : "f"(a), "f"(b));
    return r;
}
__device__ __forceinline__ void unpk2(unsigned long long v, float& a, float& b) {
    asm("mov.b64 {%0, %1}, %2;" : "=f"(a), "=f"(b) : "l"(v));
}
__device__ __forceinline__ unsigned long long fma2(
    unsigned long long a, unsigned long long b, unsigned long long c) {
    unsigned long long d;
    asm("fma.rn.f32x2 %0, %1, %2, %3;" : "=l"(d) : "l"(a), "l"(b), "l"(c));
    return d;
}
__device__ __forceinline__ unsigned long long add2(
    unsigned long long a, unsigned long long b) {
    unsigned long long d;
    asm("add.rn.f32x2 %0, %1, %2;" : "=l"(d) : "l"(a), "l"(b));
    return d;
}
__device__ __forceinline__ unsigned long long mul2(
    unsigned long long a, unsigned long long b) {
    unsigned long long d;
    asm("mul.rn.f32x2 %0, %1, %2;" : "=l"(d) : "l"(a), "l"(b));
    return d;
}

union F4U { float4 f; unsigned long long u[2]; float s[4]; };

// ---------------------------------------------------------------------------
// Kernel 1: G = H @ W^T (8192x32x1024) + row norms, G written k-major.
// R4 structure (256 threads / 32 rows, 2r x 2k per thread, reg double-buffer)
// with d-pair-packed FFMA2 accumulators: same LDS count, half the FMA instrs.
// ---------------------------------------------------------------------------
__global__ void __launch_bounds__(256) k1_proj(
    const float* __restrict__ H, const float* __restrict__ W)
{
    __shared__ float Hs[2][32][68];
    __shared__ float Ws[2][32][68];
    __shared__ float Gsm[32][33];

    const int tid = threadIdx.x;
    const int r0  = blockIdx.x * 32;
    const int ti  = tid >> 4;       // 0..15 -> rows ti*2, ti*2+1
    const int tj  = tid & 15;       // k = tj, tj+16

    float4 hreg[2], wreg[2];

    #pragma unroll
    for (int p = 0; p < 2; p++) {
        const int e  = tid + p * 256;
        const int rr = e >> 4;
        const int cc = (e & 15) * 4;
        hreg[p] = *(const float4*)(H + (size_t)(r0 + rr) * DMODEL + cc);
        wreg[p] = *(const float4*)(W + (size_t)rr * DMODEL + cc);
    }
    #pragma unroll
    for (int p = 0; p < 2; p++) {
        const int e  = tid + p * 256;
        const int rr = e >> 4;
        const int cc = (e & 15) * 4;
        *(float4*)&Hs[0][rr][cc] = hreg[p];
        *(float4*)&Ws[0][rr][cc] = wreg[p];
    }
    __syncthreads();

    // acc2[r][kk]: row ti*2+r, k = tj + 16*kk; packs (even-d, odd-d) partials.
    unsigned long long acc2[2][2] = {{0ull, 0ull}, {0ull, 0ull}};

    for (int c = 0; c < 16; c++) {
        const int buf = c & 1;

        if (c < 15) {
            const int dc = (c + 1) * 64;
            #pragma unroll
            for (int p = 0; p < 2; p++) {
                const int e  = tid + p * 256;
                const int rr = e >> 4;
                const int cc = (e & 15) * 4;
                hreg[p] = *(const float4*)(H + (size_t)(r0 + rr) * DMODEL + dc + cc);
                wreg[p] = *(const float4*)(W + (size_t)rr * DMODEL + dc + cc);
            }
        }

        #pragma unroll
        for (int d4 = 0; d4 < 64; d4 += 4) {
            F4U w0, w1;
            w0.f = *(const float4*)&Ws[buf][tj][d4];
            w1.f = *(const float4*)&Ws[buf][tj + 16][d4];
            #pragma unroll
            for (int r = 0; r < 2; r++) {
                F4U h;
                h.f = *(const float4*)&Hs[buf][ti * 2 + r][d4];
                acc2[r][0] = fma2(h.u[0], w0.u[0], acc2[r][0]);
                acc2[r][0] = fma2(h.u[1], w0.u[1], acc2[r][0]);
                acc2[r][1] = fma2(h.u[0], w1.u[0], acc2[r][1]);
                acc2[r][1] = fma2(h.u[1], w1.u[1], acc2[r][1]);
            }
        }
        __syncthreads();

        if (c < 15) {
            #pragma unroll
            for (int p = 0; p < 2; p++) {
                const int e  = tid + p * 256;
                const int rr = e >> 4;
                const int cc = (e & 15) * 4;
                *(float4*)&Hs[buf ^ 1][rr][cc] = hreg[p];
                *(float4*)&Ws[buf ^ 1][rr][cc] = wreg[p];
            }
            __syncthreads();
        }
    }

    // Horizontal add of d-pairs, stage, row-norm reduce (16 tj lanes/row).
    #pragma unroll
    for (int r = 0; r < 2; r++) {
        const int row = ti * 2 + r;
        float l0, h0, l1, h1;
        unpk2(acc2[r][0], l0, h0);
        unpk2(acc2[r][1], l1, h1);
        const float a0 = l0 + h0;
        const float a1 = l1 + h1;
        Gsm[row][tj]      = a0;
        Gsm[row][tj + 16] = a1;
        float sq = a0 * a0 + a1 * a1;
        sq += __shfl_xor_sync(0xffffffffu, sq, 1);
        sq += __shfl_xor_sync(0xffffffffu, sq, 2);
        sq += __shfl_xor_sync(0xffffffffu, sq, 4);
        sq += __shfl_xor_sync(0xffffffffu, sq, 8);
        if (tj == 0) g_Gsq[r0 + row] = sq;
    }
    __syncthreads();

    // k-major coalesced writeout (128B contiguous per k).
    #pragma unroll
    for (int e = tid; e < 32 * 32; e += 256) {
        const int k = e >> 5;
        const int i = e & 31;
        g_Gt[(size_t)k * ROWS + r0 + i] = Gsm[i][k];
    }
}

// ---------------------------------------------------------------------------
// Kernel 2: 128(i) x 64(j) tile (unchanged from R4 best). Gram in i-pair
// FFMA2; coalesced float4 tile loads from k-major G; streamed epilogue.
// ---------------------------------------------------------------------------
__global__ void __launch_bounds__(256, 4) k2_bias(
    const float* __restrict__ Bprev,
    const float* __restrict__ alpha_p,
    const float* __restrict__ beta_p,
    float* __restrict__ out)
{
    __shared__ float Gis[KDIM][128];
    __shared__ float Gjs[KDIM][64];
    __shared__ float sqi[128];
    __shared__ float sqj[64];

    const int b   = blockIdx.z;
    const int i0  = blockIdx.y * 128;
    const int j0  = blockIdx.x * 64;
    const int gi0 = b * NSEQ + i0;
    const int gj0 = b * NSEQ + j0;
    const int tid = threadIdx.x;

    const float alpha = *alpha_p;
    const float beta  = *beta_p;

    #pragma unroll
    for (int e = tid; e < KDIM * 32; e += 256) {
        const int k = e >> 5;
        const int x = (e & 31) * 4;
        *(float4*)&Gis[k][x] = *(const float4*)(g_Gt + (size_t)k * ROWS + gi0 + x);
    }
    #pragma unroll
    for (int e = tid; e < KDIM * 16; e += 256) {
        const int k = e >> 4;
        const int x = (e & 15) * 4;
        *(float4*)&Gjs[k][x] = *(const float4*)(g_Gt + (size_t)k * ROWS + gj0 + x);
    }
    if (tid < 128) sqi[tid] = g_Gsq[gi0 + tid];
    if (tid < 64)  sqj[tid] = g_Gsq[gj0 + tid];
    __syncthreads();

    const int ti = tid >> 4;    // 0..15
    const int tj = tid & 15;    // 0..15
    const int ib = ti * 8;
    const int jb = tj * 4;

    unsigned long long accp[4][4];
    #pragma unroll
    for (int ip = 0; ip < 4; ip++)
        #pragma unroll
        for (int jj = 0; jj < 4; jj++)
            accp[ip][jj] = 0ull;

    #pragma unroll 8
    for (int k = 0; k < KDIM; k++) {
        F4U gia, gib;
        gia.f = *(const float4*)&Gis[k][ib];
        gib.f = *(const float4*)&Gis[k][ib + 4];
        const float4 gj = *(const float4*)&Gjs[k][jb];
        const unsigned long long g0 = pk2(gj.x, gj.x);
        const unsigned long long g1 = pk2(gj.y, gj.y);
        const unsigned long long g2 = pk2(gj.z, gj.z);
        const unsigned long long g3 = pk2(gj.w, gj.w);

        accp[0][0] = fma2(gia.u[0], g0, accp[0][0]);
        accp[0][1] = fma2(gia.u[0], g1, accp[0][1]);
        accp[0][2] = fma2(gia.u[0], g2, accp[0][2]);
        accp[0][3] = fma2(gia.u[0], g3, accp[0][3]);
        accp[1][0] = fma2(gia.u[1], g0, accp[1][0]);
        accp[1][1] = fma2(gia.u[1], g1, accp[1][1]);
        accp[1][2] = fma2(gia.u[1], g2, accp[1][2]);
        accp[1][3] = fma2(gia.u[1], g3, accp[1][3]);
        accp[2][0] = fma2(gib.u[0], g0, accp[2][0]);
        accp[2][1] = fma2(gib.u[0], g1, accp[2][1]);
        accp[2][2] = fma2(gib.u[0], g2, accp[2][2]);
        accp[2][3] = fma2(gib.u[0], g3, accp[2][3]);
        accp[3][0] = fma2(gib.u[1], g0, accp[3][0]);
        accp[3][1] = fma2(gib.u[1], g1, accp[3][1]);
        accp[3][2] = fma2(gib.u[1], g2, accp[3][2]);
        accp[3][3] = fma2(gib.u[1], g3, accp[3][3]);
    }

    const unsigned long long alpha2   = pk2(alpha, alpha);
    const unsigned long long negbeta2 = pk2(-beta, -beta);
    const unsigned long long negtwo2  = pk2(-2.0f, -2.0f);

    unsigned long long sj2[4];
    #pragma unroll
    for (int jj = 0; jj < 4; jj++) {
        const float s = sqj[jb + jj];
        sj2[jj] = pk2(s, s);
    }

    const size_t base = ((size_t)b * NSEQ + (i0 + ib)) * NSEQ + (j0 + jb);

    #pragma unroll
    for (int ip = 0; ip < 4; ip++) {
        const int rl = 2 * ip;
        const unsigned long long si2 = pk2(sqi[ib + rl], sqi[ib + rl + 1]);

        F4U bvl, bvh;
        bvl.f = __ldcs((const float4*)(Bprev + base + (size_t)rl * NSEQ));
        bvh.f = __ldcs((const float4*)(Bprev + base + (size_t)(rl + 1) * NSEQ));

        F4U rlo, rhi;
        #pragma unroll
        for (int jj = 0; jj < 4; jj++) {
            const unsigned long long sij2 = add2(si2, sj2[jj]);
            const unsigned long long raw2 = fma2(negtwo2, accp[ip][jj], sij2);
            const unsigned long long bp2  = pk2(bvl.s[jj], bvh.s[jj]);
            const unsigned long long ab2  = mul2(alpha2, bp2);
            const unsigned long long t2   = fma2(negbeta2, raw2, ab2);
            float abl, abh, tl, th;
            unpk2(ab2, abl, abh);
            unpk2(t2, tl, th);
            rlo.s[jj] = fminf(fmaxf(fminf(abl, tl), -CLAMP_V), CLAMP_V);
            rhi.s[jj] = fminf(fmaxf(fminf(abh, th), -CLAMP_V), CLAMP_V);
        }
        __stcs((float4*)(out + base + (size_t)rl * NSEQ), rlo.f);
        __stcs((float4*)(out + base + (size_t)(rl + 1) * NSEQ), rhi.f);
    }
}

// ---------------------------------------------------------------------------
extern "C" void kernel_launch(void* const* d_in, const int* in_sizes, int n_in,
                              void* d_out, int out_size)
{
    const float* H     = (const float*)d_in[0];
    const float* Bprev = (const float*)d_in[1];
    const float* W     = (const float*)d_in[2];
    const float* alpha = (const float*)d_in[3];
    const float* beta  = (const float*)d_in[4];
    float* out = (float*)d_out;

    k1_proj<<<ROWS / 32, 256>>>(H, W);

    dim3 g2(NSEQ / 64, NSEQ / 128, BATCH);
    k2_bias<<<g2, 256>>>(Bprev, alpha, beta, out);
}

// round 13
// speedup vs baseline: 1.5780x; 1.1505x over previous
#include <cuda_runtime.h>
#include <mma.h>
#include <cstdint>

using namespace nvcuda;

#define BATCH   4
#define NSEQ    2048
#define DMODEL  1024
#define KDIM    32
#define ROWS    (BATCH * NSEQ)
#define CLAMP_V 10.0f

// Scratch: G row-major [row][32] fp32 (1 MiB, L2-resident).
__device__ float g_G[(size_t)ROWS * KDIM];

// ---- packed f32x2 helpers ---------------------------------------------------
__device__ __forceinline__ unsigned long long pk2(float a, float b) {
    unsigned long long r;
    asm("mov.b64 %0, {%1, %2};" : "=l"(r) : "f"(a), "f"(b));
    return r;
}
__device__ __forceinline__ void unpk2(unsigned long long v, float& a, float& b) {
    asm("mov.b64 {%0, %1}, %2;" : "=f"(a), "=f"(b) : "l"(v));
}
__device__ __forceinline__ unsigned long long fma2(
    unsigned long long a, unsigned long long b, unsigned long long c) {
    unsigned long long d;
    asm("fma.rn.f32x2 %0, %1, %2, %3;" : "=l"(d) : "l"(a), "l"(b), "l"(c));
    return d;
}
__device__ __forceinline__ unsigned long long add2(
    unsigned long long a, unsigned long long b) {
    unsigned long long d;
    asm("add.rn.f32x2 %0, %1, %2;" : "=l"(d) : "l"(a), "l"(b));
    return d;
}
__device__ __forceinline__ unsigned long long mul2(
    unsigned long long a, unsigned long long b) {
    unsigned long long d;
    asm("mul.rn.f32x2 %0, %1, %2;" : "=l"(d) : "l"(a), "l"(b));
    return d;
}

union F4U { float4 f; unsigned long long u[2]; float s[4]; };

// ---- cp.async helpers -------------------------------------------------------
__device__ __forceinline__ void cpasync16(void* smem_ptr, const void* gmem_ptr) {
    unsigned int s = (unsigned int)__cvta_generic_to_shared(smem_ptr);
    asm volatile("cp.async.cg.shared.global [%0], [%1], 16;\n"
                 :: "r"(s), "l"(gmem_ptr) : "memory");
}
__device__ __forceinline__ void cpasync_commit() {
    asm volatile("cp.async.commit_group;\n" ::: "memory");
}
__device__ __forceinline__ void cpasync_wait1() {
    asm volatile("cp.async.wait_group 1;\n" ::: "memory");
}
__device__ __forceinline__ void cpasync_wait0() {
    asm volatile("cp.async.wait_group 0;\n" ::: "memory");
}

// ---- tf32 fragment conversion ----------------------------------------------
template <class Frag>
__device__ __forceinline__ void frag_to_tf32(Frag& f) {
    #pragma unroll
    for (int i = 0; i < f.num_elements; i++)
        f.x[i] = wmma::__float_to_tf32(f.x[i]);
}

// ---------------------------------------------------------------------------
// Kernel 1: G = H @ W^T (8192x32x1024) via tf32 WMMA m16n16k8.
// 128 blocks x 64 rows, 256 threads (8 warps = 4 m-tiles x 2 n-tiles).
// 3-stage cp.async pipeline over d-chunks of 32. Accumulators persist.
// ---------------------------------------------------------------------------
#define K1_STAGE_D 32

__device__ __forceinline__ void k1_issue_stage(
    int s, int dc, int tid, int r0,
    const float* __restrict__ H, const float* __restrict__ W,
    float (*Hs)[64][40], float (*Ws)[32][40])
{
    // H: 64 rows x 32 cols = 512 x 16B, 2 per thread.
    #pragma unroll
    for (int p = 0; p < 2; p++) {
        const int e  = tid + p * 256;
        const int rr = e >> 3;
        const int cc = (e & 7) * 4;
        cpasync16(&Hs[s][rr][cc], H + (size_t)(r0 + rr) * DMODEL + dc + cc);
    }
    // W: 32 rows x 32 cols = 256 x 16B, 1 per thread.
    {
        const int rr = tid >> 3;
        const int cc = (tid & 7) * 4;
        cpasync16(&Ws[s][rr][cc], W + (size_t)rr * DMODEL + dc + cc);
    }
    cpasync_commit();
}

__global__ void __launch_bounds__(256) k1_proj(
    const float* __restrict__ H, const float* __restrict__ W)
{
    __shared__ float Hs[3][64][40];
    __shared__ float Ws[3][32][40];

    const int tid = threadIdx.x;
    const int r0  = blockIdx.x * 64;
    const int w   = tid >> 5;
    const int mt  = w & 3;      // m-tile: rows mt*16..+15
    const int nt  = w >> 2;     // n-tile: k-outputs nt*16..+15

    k1_issue_stage(0, 0, tid, r0, H, W, Hs, Ws);
    k1_issue_stage(1, K1_STAGE_D, tid, r0, H, W, Hs, Ws);

    wmma::fragment<wmma::accumulator, 16, 16, 8, float> acc;
    wmma::fill_fragment(acc, 0.0f);

    const int NCHUNK = DMODEL / K1_STAGE_D;   // 32
    for (int c = 0; c < NCHUNK; c++) {
        if (c < NCHUNK - 1) cpasync_wait1(); else cpasync_wait0();
        __syncthreads();

        if (c + 2 < NCHUNK)
            k1_issue_stage((c + 2) % 3, (c + 2) * K1_STAGE_D, tid, r0, H, W, Hs, Ws);

        const int buf = c % 3;
        #pragma unroll
        for (int ks = 0; ks < K1_STAGE_D / 8; ks++) {
            wmma::fragment<wmma::matrix_a, 16, 16, 8, wmma::precision::tf32,
                           wmma::row_major> a;
            wmma::fragment<wmma::matrix_b, 16, 16, 8, wmma::precision::tf32,
                           wmma::col_major> bf;
            wmma::load_matrix_sync(a, &Hs[buf][mt * 16][ks * 8], 40);
            wmma::load_matrix_sync(bf, &Ws[buf][nt * 16][ks * 8], 40);
            frag_to_tf32(a);
            frag_to_tf32(bf);
            wmma::mma_sync(acc, a, bf, acc);
        }
    }

    // Direct fp32 store to G (row-major, ld = 32).
    wmma::store_matrix_sync(g_G + (size_t)(r0 + mt * 16) * KDIM + nt * 16,
                            acc, KDIM, wmma::mem_row_major);
}

// ---------------------------------------------------------------------------
// Kernel 2: 64x64 tile. Gram via tf32 WMMA (16 tiles, 2 per warp) staged
// through smem Cs; norms computed in-block; packed fp32 epilogue.
// ---------------------------------------------------------------------------
__global__ void __launch_bounds__(256) k2_bias(
    const float* __restrict__ Bprev,
    const float* __restrict__ alpha_p,
    const float* __restrict__ beta_p,
    float* __restrict__ out)
{
    __shared__ float Gi[64][36];
    __shared__ float Gj[64][36];
    __shared__ float Cs[64][68];
    __shared__ float sqi[64];
    __shared__ float sqj[64];

    const int b   = blockIdx.z;
    const int i0  = blockIdx.y * 64;
    const int j0  = blockIdx.x * 64;
    const int gi0 = b * NSEQ + i0;
    const int gj0 = b * NSEQ + j0;
    const int tid = threadIdx.x;

    const float alpha = *alpha_p;
    const float beta  = *beta_p;

    // Load G tiles (row-major fp32, coalesced float4).
    #pragma unroll
    for (int e = tid; e < 512; e += 256) {
        const int r  = e >> 3;
        const int c4 = (e & 7) * 4;
        *(float4*)&Gi[r][c4] = *(const float4*)(g_G + (size_t)(gi0 + r) * KDIM + c4);
        *(float4*)&Gj[r][c4] = *(const float4*)(g_G + (size_t)(gj0 + r) * KDIM + c4);
    }
    __syncthreads();

    // Row norms from smem tiles.
    if (tid < 64) {
        float s = 0.f;
        #pragma unroll
        for (int k = 0; k < KDIM; k++) { const float v = Gi[tid][k]; s += v * v; }
        sqi[tid] = s;
    } else if (tid < 128) {
        const int r = tid - 64;
        float s = 0.f;
        #pragma unroll
        for (int k = 0; k < KDIM; k++) { const float v = Gj[r][k]; s += v * v; }
        sqj[r] = s;
    }

    // Gram: warp w -> m-tile (w&3), n-tiles {(w>>2)*2, (w>>2)*2+1}.
    const int w   = tid >> 5;
    const int mt  = w & 3;
    const int ntb = (w >> 2) * 2;

    wmma::fragment<wmma::accumulator, 16, 16, 8, float> acc0, acc1;
    wmma::fill_fragment(acc0, 0.0f);
    wmma::fill_fragment(acc1, 0.0f);

    #pragma unroll
    for (int ks = 0; ks < KDIM / 8; ks++) {
        wmma::fragment<wmma::matrix_a, 16, 16, 8, wmma::precision::tf32,
                       wmma::row_major> a;
        wmma::load_matrix_sync(a, &Gi[mt * 16][ks * 8], 36);
        frag_to_tf32(a);

        wmma::fragment<wmma::matrix_b, 16, 16, 8, wmma::precision::tf32,
                       wmma::col_major> bf;
        wmma::load_matrix_sync(bf, &Gj[ntb * 16][ks * 8], 36);
        frag_to_tf32(bf);
        wmma::mma_sync(acc0, a, bf, acc0);

        wmma::load_matrix_sync(bf, &Gj[(ntb + 1) * 16][ks * 8], 36);
        frag_to_tf32(bf);
        wmma::mma_sync(acc1, a, bf, acc1);
    }

    wmma::store_matrix_sync(&Cs[mt * 16][ntb * 16], acc0, 68, wmma::mem_row_major);
    wmma::store_matrix_sync(&Cs[mt * 16][(ntb + 1) * 16], acc1, 68, wmma::mem_row_major);
    __syncthreads();

    // Epilogue: raw = si + sj - 2*gram; ab = alpha*b;
    // result = clamp(min(ab, fma(-beta, raw, ab)), -10, 10).
    const int ti = tid >> 4;     // 0..15 -> rows ib..ib+3
    const int tj = tid & 15;     // 0..15 -> cols jb..jb+3
    const int ib = ti * 4;
    const int jb = tj * 4;

    const unsigned long long alpha2   = pk2(alpha, alpha);
    const unsigned long long negbeta2 = pk2(-beta, -beta);
    const unsigned long long negtwo2  = pk2(-2.0f, -2.0f);

    unsigned long long sj2[4];
    #pragma unroll
    for (int jj = 0; jj < 4; jj++) {
        const float s = sqj[jb + jj];
        sj2[jj] = pk2(s, s);
    }

    const size_t base = ((size_t)b * NSEQ + (i0 + ib)) * NSEQ + (j0 + jb);

    #pragma unroll
    for (int ip = 0; ip < 2; ip++) {
        const int rl = ib + 2 * ip;
        const unsigned long long si2 = pk2(sqi[rl], sqi[rl + 1]);

        F4U c0, c1;
        c0.f = *(const float4*)&Cs[rl][jb];
        c1.f = *(const float4*)&Cs[rl + 1][jb];

        F4U bvl, bvh;
        bvl.f = __ldcs((const float4*)(Bprev + base + (size_t)(2 * ip) * NSEQ));
        bvh.f = __ldcs((const float4*)(Bprev + base + (size_t)(2 * ip + 1) * NSEQ));

        F4U rlo, rhi;
        #pragma unroll
        for (int jj = 0; jj < 4; jj++) {
            const unsigned long long accp = pk2(c0.s[jj], c1.s[jj]);
            const unsigned long long sij2 = add2(si2, sj2[jj]);
            const unsigned long long raw2 = fma2(negtwo2, accp, sij2);
            const unsigned long long bp2  = pk2(bvl.s[jj], bvh.s[jj]);
            const unsigned long long ab2  = mul2(alpha2, bp2);
            const unsigned long long t2   = fma2(negbeta2, raw2, ab2);
            float abl, abh, tl, th;
            unpk2(ab2, abl, abh);
            unpk2(t2, tl, th);
            rlo.s[jj] = fminf(fmaxf(fminf(abl, tl), -CLAMP_V), CLAMP_V);
            rhi.s[jj] = fminf(fmaxf(fminf(abh, th), -CLAMP_V), CLAMP_V);
        }
        __stcs((float4*)(out + base + (size_t)(2 * ip) * NSEQ), rlo.f);
        __stcs((float4*)(out + base + (size_t)(2 * ip + 1) * NSEQ), rhi.f);
    }
}

// ---------------------------------------------------------------------------
extern "C" void kernel_launch(void* const* d_in, const int* in_sizes, int n_in,
                              void* d_out, int out_size)
{
    const float* H     = (const float*)d_in[0];
    const float* Bprev = (const float*)d_in[1];
    const float* W     = (const float*)d_in[2];
    const float* alpha = (const float*)d_in[3];
    const float* beta  = (const float*)d_in[4];
    float* out = (float*)d_out;

    k1_proj<<<ROWS / 64, 256>>>(H, W);

    dim3 g2(NSEQ / 64, NSEQ / 64, BATCH);
    k2_bias<<<g2, 256>>>(Bprev, alpha, beta, out);
}